// round 1
// baseline (speedup 1.0000x reference)
#include <cuda_runtime.h>
#include <cstdint>

#define NB   8
#define NL   2048
#define NK   16
#define NATT 64
#define NEMB 32
#define NOUT 128

// ---------------- scratch (device globals; no allocations allowed) ----------
__device__ int   g_nidx[NB * NL * NK];                 // 1 MB
__device__ float g_outer[(size_t)NB * NL * 2048];      // 134 MB
__device__ float g_embsum[NB * NL * NEMB];             // 2 MB

// ============================================================================
// Kernel A: KNN top-16 (smallest d2, ties -> lower index via packed u64 key)
// grid 128 blocks x 128 threads; block = (batch b, 128 queries)
// ============================================================================
__global__ __launch_bounds__(128) void knn_kernel(const float* __restrict__ frame)
{
    __shared__ float4 cent[NL];   // 32 KB: x,y,z,|c|^2

    const int b   = blockIdx.x >> 4;   // 16 blocks per batch
    const int qb  = blockIdx.x & 15;
    const int tid = threadIdx.x;

    for (int m = tid; m < NL; m += 128) {
        const float* p = frame + ((size_t)(b * NL + m)) * 12;
        float x = p[0], y = p[1], z = p[2];
        float sq = fmaf(x, x, fmaf(y, y, z * z));
        cent[m] = make_float4(x, y, z, sq);
    }
    __syncthreads();

    const int q = qb * 128 + tid;
    const float4 cq = cent[q];

    unsigned long long list[16];
#pragma unroll
    for (int i = 0; i < 16; i++) list[i] = 0xFFFFFFFFFFFFFFFFull;

#pragma unroll 4
    for (int m = 0; m < NL; m++) {
        float4 c = cent[m];
        float dot = fmaf(cq.x, c.x, fmaf(cq.y, c.y, cq.z * c.z));
        float d2  = fmaf(-2.0f, dot, cq.w + c.w);
        d2 = fmaxf(d2, 0.0f);
        unsigned long long cand =
            ((unsigned long long)__float_as_uint(d2) << 32) | (unsigned)m;
        if (cand < list[15]) {
#pragma unroll
            for (int i = 0; i < 16; i++) {
                unsigned long long h = list[i];
                bool lt = cand < h;
                list[i] = lt ? cand : h;
                cand    = lt ? h : cand;
            }
        }
    }

    int* o = g_nidx + ((size_t)(b * NL + q)) * NK;
#pragma unroll
    for (int i = 0; i < 16; i++) o[i] = (int)(unsigned)(list[i] & 0xFFFFFFFFull);
}

// ============================================================================
// Kernel B: coords -> gaussian emb -> outer(32x64) + embsum(32) per (b,l)
// grid 16384 blocks x 128 threads
// ============================================================================
__global__ __launch_bounds__(128) void feat_kernel(
    const float* __restrict__ attr,
    const float* __restrict__ frame,
    const int*   __restrict__ aidx,
    const float* __restrict__ gkc,    // (7,32)
    const float* __restrict__ gkp)    // (7,7,32)
{
    __shared__ int   s_nidx[NK];
    __shared__ float s_coords[NK][8];
    __shared__ float s_cent[32][9];    // [n][d], pad 9 for bank-conflict-free
    __shared__ float s_prec[32][49];   // [n][d*7+e], stride 49 coprime w/ 32
    __shared__ float s_attr[NK][64];
    __shared__ float s_emb[NK][32];

    const int bl  = blockIdx.x;        // global (b,l)
    const int b   = bl >> 11;
    const int tid = threadIdx.x;

    if (tid < NK) s_nidx[tid] = g_nidx[(size_t)bl * NK + tid];
    for (int i = tid; i < 7 * 32; i += 128)         // i = d*32+n
        s_cent[i & 31][i >> 5] = gkc[i];
    for (int i = tid; i < 49 * 32; i += 128)        // i = (d*7+e)*32+n
        s_prec[i & 31][i >> 5] = gkp[i];
    __syncthreads();

    // gather neighbor attributes
    for (int i = tid; i < NK * 64; i += 128) {
        int k = i >> 6, j = i & 63;
        s_attr[k][j] = attr[((size_t)(b * NL + s_nidx[k])) * 64 + j];
    }

    // coords: 16 threads, one neighbor each
    if (tid < NK) {
        const int k = tid;
        const int m = s_nidx[k];
        const size_t gs = (size_t)bl * 12;
        const size_t gn = (size_t)(b * NL + m) * 12;

        float cx = frame[gs + 0], cy = frame[gs + 1], cz = frame[gs + 2];
        float r0x = frame[gs + 3], r0y = frame[gs + 4],  r0z = frame[gs + 5];
        float r1x = frame[gs + 6], r1y = frame[gs + 7],  r1z = frame[gs + 8];
        float r2x = frame[gs + 9], r2y = frame[gs + 10], r2z = frame[gs + 11]; // z_self

        float dx = frame[gn + 0] - cx, dy = frame[gn + 1] - cy, dz = frame[gn + 2] - cz;
        float znx = frame[gn + 9], zny = frame[gn + 10], znz = frame[gn + 11]; // z_nei

        float e0 = dx * r0x + dy * r0y + dz * r0z;
        float e1 = dx * r1x + dy * r1y + dz * r1z;
        float e2 = dx * r2x + dy * r2y + dz * r2z;   // delta . z_self

        float idxs = (float)aidx[bl];
        float idxn = (float)aidx[b * NL + m];
        float idist = fminf(fabsf(idxn - idxs), 8.0f);

        float zz   = znx * r2x + zny * r2y + znz * r2z;
        float dist = sqrtf(dx * dx + dy * dy + dz * dz + 1e-6f);
        float ddz  = e2 / dist;
        float zdd  = (znx * dx + zny * dy + znz * dz) / dist;

        s_coords[k][0] = e0;  s_coords[k][1] = e1;  s_coords[k][2] = e2;
        s_coords[k][3] = idist; s_coords[k][4] = zz;
        s_coords[k][5] = ddz;   s_coords[k][6] = zdd; s_coords[k][7] = 0.0f;
    }
    __syncthreads();

    // gaussian kernel: 512 (k,n) items
#pragma unroll
    for (int it = tid; it < NK * 32; it += 128) {
        int k = it >> 5, n = it & 31;
        float y0 = 0, y1 = 0, y2 = 0, y3 = 0, y4 = 0, y5 = 0, y6 = 0;
#pragma unroll
        for (int d = 0; d < 7; d++) {
            float diff = s_coords[k][d] - s_cent[n][d];
            const float* p = &s_prec[n][d * 7];
            y0 = fmaf(diff, p[0], y0);
            y1 = fmaf(diff, p[1], y1);
            y2 = fmaf(diff, p[2], y2);
            y3 = fmaf(diff, p[3], y3);
            y4 = fmaf(diff, p[4], y4);
            y5 = fmaf(diff, p[5], y5);
            y6 = fmaf(diff, p[6], y6);
        }
        float s = y0 * y0 + y1 * y1 + y2 * y2 + y3 * y3 + y4 * y4 + y5 * y5 + y6 * y6;
        s_emb[k][n] = __expf(-0.5f * s);
    }
    __syncthreads();

    // embsum
    if (tid < 32) {
        float s = 0.0f;
#pragma unroll
        for (int k = 0; k < NK; k++) s += s_emb[k][tid];
        g_embsum[(size_t)bl * 32 + tid] = s;
    }

    // outer[i][j] = sum_k emb[k][i] * attr[k][j]; thread: j = tid&63, i in iq*16..+15
    const int j  = tid & 63;
    const int iq = tid >> 6;
    float acc[16];
#pragma unroll
    for (int r = 0; r < 16; r++) acc[r] = 0.0f;
#pragma unroll
    for (int k = 0; k < NK; k++) {
        float a = s_attr[k][j];
        const float4* ep = (const float4*)&s_emb[k][iq * 16];
        float4 ea = ep[0], eb = ep[1], ec = ep[2], ed = ep[3];
        acc[0]  = fmaf(ea.x, a, acc[0]);  acc[1]  = fmaf(ea.y, a, acc[1]);
        acc[2]  = fmaf(ea.z, a, acc[2]);  acc[3]  = fmaf(ea.w, a, acc[3]);
        acc[4]  = fmaf(eb.x, a, acc[4]);  acc[5]  = fmaf(eb.y, a, acc[5]);
        acc[6]  = fmaf(eb.z, a, acc[6]);  acc[7]  = fmaf(eb.w, a, acc[7]);
        acc[8]  = fmaf(ec.x, a, acc[8]);  acc[9]  = fmaf(ec.y, a, acc[9]);
        acc[10] = fmaf(ec.z, a, acc[10]); acc[11] = fmaf(ec.w, a, acc[11]);
        acc[12] = fmaf(ed.x, a, acc[12]); acc[13] = fmaf(ed.y, a, acc[13]);
        acc[14] = fmaf(ed.z, a, acc[14]); acc[15] = fmaf(ed.w, a, acc[15]);
    }
    size_t base = (size_t)bl * 2048 + (size_t)iq * 1024 + j;
#pragma unroll
    for (int r = 0; r < 16; r++) g_outer[base + (size_t)r * 64] = acc[r];
}

// ============================================================================
// Kernel C: out(16384x128) = outer(16384x2048) @ W12(2048x128)
//                            + embsum(16384x32) @ K1(32x128) + bias
// grid 128 blocks x 256 threads; BM=128, BN=128, BK=32; 8x8 per thread
// ============================================================================
__global__ __launch_bounds__(256) void gemm_kernel(
    const float* __restrict__ W12,   // (2048,128) row-major
    const float* __restrict__ K1,    // (32,128)
    const float* __restrict__ bias,  // (128)
    float*       __restrict__ out)   // (16384,128)
{
    __shared__ float As[32][132];    // [k][row]
    __shared__ float Bs[32][132];    // [k][col]

    const int tid = threadIdx.x;
    const int tx  = tid & 15;
    const int ty  = tid >> 4;
    const int rowBase = blockIdx.x * 128;

    float acc[8][8];
#pragma unroll
    for (int i = 0; i < 8; i++)
#pragma unroll
        for (int j = 0; j < 8; j++) acc[i][j] = 0.0f;

    for (int kt = 0; kt < 64; kt++) {
#pragma unroll
        for (int s = 0; s < 4; s++) {
            int item = tid + s * 256;
            int r  = item >> 3;
            int c4 = (item & 7) * 4;
            float4 v = *(const float4*)&g_outer[(size_t)(rowBase + r) * 2048 + kt * 32 + c4];
            As[c4 + 0][r] = v.x; As[c4 + 1][r] = v.y;
            As[c4 + 2][r] = v.z; As[c4 + 3][r] = v.w;
        }
#pragma unroll
        for (int s = 0; s < 4; s++) {
            int item = tid + s * 256;
            int k  = item >> 5;
            int f4 = (item & 31) * 4;
            *(float4*)&Bs[k][f4] = *(const float4*)&W12[(size_t)(kt * 32 + k) * 128 + f4];
        }
        __syncthreads();

#pragma unroll 4
        for (int k = 0; k < 32; k++) {
            float4 a0 = *(const float4*)&As[k][ty * 4];
            float4 a1 = *(const float4*)&As[k][64 + ty * 4];
            float4 b0 = *(const float4*)&Bs[k][tx * 4];
            float4 b1 = *(const float4*)&Bs[k][64 + tx * 4];
            float av[8] = {a0.x, a0.y, a0.z, a0.w, a1.x, a1.y, a1.z, a1.w};
            float bv[8] = {b0.x, b0.y, b0.z, b0.w, b1.x, b1.y, b1.z, b1.w};
#pragma unroll
            for (int i = 0; i < 8; i++)
#pragma unroll
                for (int j = 0; j < 8; j++)
                    acc[i][j] = fmaf(av[i], bv[j], acc[i][j]);
        }
        __syncthreads();
    }

    // ---- epilogue: embsum @ K1, staged in smem (reuse As/Bs) ----
    float* Es = &As[0][0];                       // Es[row*33 + i], 128*33 = 4224
    for (int s = tid; s < 128 * 32; s += 256) {
        int r = s >> 5, i2 = s & 31;
        Es[r * 33 + i2] = g_embsum[(size_t)(rowBase + r) * 32 + i2];
    }
    for (int s = tid; s < 32 * 128; s += 256) {
        int k = s >> 7, f = s & 127;
        Bs[k][f] = K1[s];
    }
    __syncthreads();

    int rr[8], cc[8];
#pragma unroll
    for (int i = 0; i < 4; i++) { rr[i] = ty * 4 + i; rr[i + 4] = 64 + ty * 4 + i; }
#pragma unroll
    for (int j = 0; j < 4; j++) { cc[j] = tx * 4 + j; cc[j + 4] = 64 + tx * 4 + j; }

#pragma unroll 8
    for (int t = 0; t < 32; t++) {
        float ev[8], wv[8];
#pragma unroll
        for (int i = 0; i < 8; i++) ev[i] = Es[rr[i] * 33 + t];
#pragma unroll
        for (int j = 0; j < 8; j++) wv[j] = Bs[t][cc[j]];
#pragma unroll
        for (int i = 0; i < 8; i++)
#pragma unroll
            for (int j = 0; j < 8; j++)
                acc[i][j] = fmaf(ev[i], wv[j], acc[i][j]);
    }

    float bv[8];
#pragma unroll
    for (int j = 0; j < 8; j++) bv[j] = bias[cc[j]];

#pragma unroll
    for (int i = 0; i < 8; i++) {
        size_t ro = (size_t)(rowBase + rr[i]) * 128;
#pragma unroll
        for (int j = 0; j < 8; j++)
            out[ro + cc[j]] = acc[i][j] + bv[j];
    }
}

// ============================================================================
extern "C" void kernel_launch(void* const* d_in, const int* in_sizes, int n_in,
                              void* d_out, int out_size)
{
    const float* attr  = (const float*)d_in[0];
    const float* frame = (const float*)d_in[1];
    const int*   aidx  = (const int*)  d_in[2];
    // d_in[3] = labels (unused)
    const float* gkc   = (const float*)d_in[4];
    const float* gkp   = (const float*)d_in[5];
    const float* W12   = (const float*)d_in[6];
    const float* K1    = (const float*)d_in[7];
    const float* bias  = (const float*)d_in[8];
    float* out = (float*)d_out;

    knn_kernel<<<128, 128>>>(frame);
    feat_kernel<<<NB * NL, 128>>>(attr, frame, aidx, gkc, gkp);
    gemm_kernel<<<128, 256>>>(W12, K1, bias, out);
}

// round 3
// speedup vs baseline: 1.1140x; 1.1140x over previous
#include <cuda_runtime.h>
#include <cstdint>

#define NB   8
#define NL   2048
#define NK   16
#define NATT 64
#define NEMB 32
#define NOUT 128

typedef unsigned long long ull;

// ---------------- scratch (device globals; no allocations allowed) ----------
__device__ int    g_nidx[NB * NL * NK];                 // 1 MB
__device__ float  g_outer[(size_t)NB * NL * 2048];      // 134 MB
__device__ float  g_embsum[NB * NL * NEMB];             // 2 MB
__device__ float4 g_cent[NB * NL];                      // 512 KB packed centers

// ---------------- f32x2 helpers (Blackwell FFMA2 path) ----------------------
__device__ __forceinline__ void fma2(ull& d, ull a, ull b) {
    asm("fma.rn.f32x2 %0, %1, %2, %3;" : "=l"(d) : "l"(a), "l"(b), "l"(d));
}
__device__ __forceinline__ ull pack2(float x, float y) {
    ull r; asm("mov.b64 %0, {%1, %2};" : "=l"(r) : "f"(x), "f"(y)); return r;
}
__device__ __forceinline__ float2 unpack2(ull v) {
    float2 f; asm("mov.b64 {%0, %1}, %2;" : "=f"(f.x), "=f"(f.y) : "l"(v)); return f;
}

// ============================================================================
// Kernel A0: pack centers (x,y,z,|c|^2) once
// ============================================================================
__global__ __launch_bounds__(256) void pack_centers(const float* __restrict__ frame)
{
    int i = blockIdx.x * 256 + threadIdx.x;   // 0 .. 16383
    const float* p = frame + (size_t)i * 12;
    float x = p[0], y = p[1], z = p[2];
    float sq = fmaf(x, x, fmaf(y, y, z * z));
    g_cent[i] = make_float4(x, y, z, sq);
}

// ============================================================================
// Kernel A: KNN, warp-per-query. Lane keeps top-16 of its 64 candidates
// (coalesced, m = r*32+lane), then warp merge via smem sorted lists.
// grid 2048 blocks x 256 threads (8 warps = 8 queries per block)
// ============================================================================
__global__ __launch_bounds__(256) void knn_kernel()
{
    __shared__ ull s_merge[8][32 * 16];

    const int w    = threadIdx.x >> 5;
    const int lane = threadIdx.x & 31;
    const int q    = blockIdx.x * 8 + w;      // global (b,l)
    const int b    = q >> 11;

    const float4* __restrict__ cent = g_cent + b * NL;
    const float4 cq = cent[q & 2047];

    float dl[16];
    int   il[16];
#pragma unroll
    for (int s = 0; s < 16; s++) { dl[s] = __int_as_float(0x7F800000); il[s] = -1; }

#pragma unroll 4
    for (int r = 0; r < 64; r++) {
        const int m = r * 32 + lane;
        float4 c = cent[m];
        float dot = fmaf(cq.x, c.x, fmaf(cq.y, c.y, cq.z * c.z));
        float d2  = fmaf(-2.0f, dot, cq.w + c.w);
        d2 = fmaxf(d2, 0.0f);
        if (d2 < dl[15]) {
            float cd = d2; int ci = m;
#pragma unroll
            for (int s = 0; s < 16; s++) {
                bool  lt = cd < dl[s];
                float td = dl[s]; int ti = il[s];
                dl[s] = lt ? cd : td;  il[s] = lt ? ci : ti;
                cd    = lt ? td : cd;  ci    = lt ? ti : ci;
            }
        }
    }

    // dump sorted per-lane lists (packed: d2 bits hi, idx lo; d2 >= 0)
    ull* my = &s_merge[w][lane * 16];
#pragma unroll
    for (int s = 0; s < 16; s++)
        my[s] = ((ull)__float_as_uint(dl[s]) << 32) | (unsigned)il[s];
    __syncwarp();

    // 16-round extraction of the global minimum (keys unique: idx in low bits)
    int p = 0;
    ull h = my[0];
    int* o = g_nidx + (size_t)q * NK;
#pragma unroll
    for (int r = 0; r < 16; r++) {
        ull v = h;
#pragma unroll
        for (int off = 16; off > 0; off >>= 1) {
            ull ov = __shfl_down_sync(0xFFFFFFFFu, v, off);
            v = ov < v ? ov : v;
        }
        v = __shfl_sync(0xFFFFFFFFu, v, 0);
        if (h == v) {                       // exactly one owner lane
            o[r] = (int)(unsigned)(v & 0xFFFFFFFFull);
            p++;
            h = (p < 16) ? my[p] : 0xFFFFFFFFFFFFFFFFull;
        }
    }
}

// ============================================================================
// Kernel B: coords -> gaussian emb -> outer(32x64) + embsum(32) per (b,l)
// grid 16384 blocks x 128 threads
// ============================================================================
__global__ __launch_bounds__(128) void feat_kernel(
    const float* __restrict__ attr,
    const float* __restrict__ frame,
    const int*   __restrict__ aidx,
    const float* __restrict__ gkc,    // (7,32)
    const float* __restrict__ gkp)    // (7,7,32)
{
    __shared__ int   s_nidx[NK];
    __shared__ float s_coords[NK][8];
    __shared__ float s_cent[32][9];
    __shared__ float s_prec[32][49];
    __shared__ float s_attr[NK][64];
    __shared__ float s_emb[NK][32];

    const int bl  = blockIdx.x;
    const int b   = bl >> 11;
    const int tid = threadIdx.x;

    if (tid < NK) s_nidx[tid] = g_nidx[(size_t)bl * NK + tid];
    for (int i = tid; i < 7 * 32; i += 128)
        s_cent[i & 31][i >> 5] = gkc[i];
    for (int i = tid; i < 49 * 32; i += 128)
        s_prec[i & 31][i >> 5] = gkp[i];
    __syncthreads();

    for (int i = tid; i < NK * 64; i += 128) {
        int k = i >> 6, j = i & 63;
        s_attr[k][j] = attr[((size_t)(b * NL + s_nidx[k])) * 64 + j];
    }

    if (tid < NK) {
        const int k = tid;
        const int m = s_nidx[k];
        const size_t gs = (size_t)bl * 12;
        const size_t gn = (size_t)(b * NL + m) * 12;

        float cx = frame[gs + 0], cy = frame[gs + 1], cz = frame[gs + 2];
        float r0x = frame[gs + 3], r0y = frame[gs + 4],  r0z = frame[gs + 5];
        float r1x = frame[gs + 6], r1y = frame[gs + 7],  r1z = frame[gs + 8];
        float r2x = frame[gs + 9], r2y = frame[gs + 10], r2z = frame[gs + 11];

        float dx = frame[gn + 0] - cx, dy = frame[gn + 1] - cy, dz = frame[gn + 2] - cz;
        float znx = frame[gn + 9], zny = frame[gn + 10], znz = frame[gn + 11];

        float e0 = dx * r0x + dy * r0y + dz * r0z;
        float e1 = dx * r1x + dy * r1y + dz * r1z;
        float e2 = dx * r2x + dy * r2y + dz * r2z;

        float idxs = (float)aidx[bl];
        float idxn = (float)aidx[b * NL + m];
        float idist = fminf(fabsf(idxn - idxs), 8.0f);

        float zz   = znx * r2x + zny * r2y + znz * r2z;
        float dist = sqrtf(dx * dx + dy * dy + dz * dz + 1e-6f);
        float ddz  = e2 / dist;
        float zdd  = (znx * dx + zny * dy + znz * dz) / dist;

        s_coords[k][0] = e0;  s_coords[k][1] = e1;  s_coords[k][2] = e2;
        s_coords[k][3] = idist; s_coords[k][4] = zz;
        s_coords[k][5] = ddz;   s_coords[k][6] = zdd; s_coords[k][7] = 0.0f;
    }
    __syncthreads();

#pragma unroll
    for (int it = tid; it < NK * 32; it += 128) {
        int k = it >> 5, n = it & 31;
        float y0 = 0, y1 = 0, y2 = 0, y3 = 0, y4 = 0, y5 = 0, y6 = 0;
#pragma unroll
        for (int d = 0; d < 7; d++) {
            float diff = s_coords[k][d] - s_cent[n][d];
            const float* pp = &s_prec[n][d * 7];
            y0 = fmaf(diff, pp[0], y0);
            y1 = fmaf(diff, pp[1], y1);
            y2 = fmaf(diff, pp[2], y2);
            y3 = fmaf(diff, pp[3], y3);
            y4 = fmaf(diff, pp[4], y4);
            y5 = fmaf(diff, pp[5], y5);
            y6 = fmaf(diff, pp[6], y6);
        }
        float s = y0 * y0 + y1 * y1 + y2 * y2 + y3 * y3 + y4 * y4 + y5 * y5 + y6 * y6;
        s_emb[k][n] = __expf(-0.5f * s);
    }
    __syncthreads();

    if (tid < 32) {
        float s = 0.0f;
#pragma unroll
        for (int k = 0; k < NK; k++) s += s_emb[k][tid];
        g_embsum[(size_t)bl * 32 + tid] = s;
    }

    // outer[i][j] = sum_k emb[k][i]*attr[k][j]; f32x2 pairs along i
    const int j  = tid & 63;
    const int iq = tid >> 6;
    ull acc2[8];
#pragma unroll
    for (int r = 0; r < 8; r++) acc2[r] = 0ull;
#pragma unroll
    for (int k = 0; k < NK; k++) {
        float a = s_attr[k][j];
        ull ap = pack2(a, a);
        const ulonglong2* ep = (const ulonglong2*)&s_emb[k][iq * 16];
        ulonglong2 e0 = ep[0], e1 = ep[1];
        fma2(acc2[0], e0.x, ap); fma2(acc2[1], e0.y, ap);
        fma2(acc2[2], e1.x, ap); fma2(acc2[3], e1.y, ap);
        ulonglong2 e2 = ep[2], e3 = ep[3];
        fma2(acc2[4], e2.x, ap); fma2(acc2[5], e2.y, ap);
        fma2(acc2[6], e3.x, ap); fma2(acc2[7], e3.y, ap);
    }
    size_t base = (size_t)bl * 2048 + (size_t)iq * 1024 + j;
#pragma unroll
    for (int r = 0; r < 8; r++) {
        float2 f = unpack2(acc2[r]);
        g_outer[base + (size_t)(2 * r) * 64]     = f.x;
        g_outer[base + (size_t)(2 * r + 1) * 64] = f.y;
    }
}

// ============================================================================
// Kernel C: out = outer @ W12 + embsum @ K1 + bias, FFMA2 inner product
// BM=64, BN=128, BK=32; 256 blocks x 128 threads; 8x8 per thread (8x4 f32x2)
// ============================================================================
__global__ __launch_bounds__(128) void gemm_kernel(
    const float* __restrict__ W12,   // (2048,128)
    const float* __restrict__ K1,    // (32,128)
    const float* __restrict__ bias,  // (128)
    float*       __restrict__ out)   // (16384,128)
{
    __shared__ float As[32][68];     // [k][row]
    __shared__ float Bs[32][132];    // [k][col]

    const int tid = threadIdx.x;
    const int tx  = tid & 15;        // col group: tx*8 .. +7
    const int ty  = tid >> 4;        // row group: ty*8 .. +7
    const int rowBase = blockIdx.x * 64;

    ull acc[8][4];
#pragma unroll
    for (int i = 0; i < 8; i++)
#pragma unroll
        for (int j = 0; j < 4; j++) acc[i][j] = 0ull;

    for (int kt = 0; kt < 64; kt++) {
#pragma unroll
        for (int s = 0; s < 4; s++) {
            int item = tid + s * 128;
            int r  = item >> 3;
            int c4 = (item & 7) * 4;
            float4 v = *(const float4*)&g_outer[(size_t)(rowBase + r) * 2048 + kt * 32 + c4];
            As[c4 + 0][r] = v.x; As[c4 + 1][r] = v.y;
            As[c4 + 2][r] = v.z; As[c4 + 3][r] = v.w;
        }
#pragma unroll
        for (int s = 0; s < 8; s++) {
            int item = tid + s * 128;
            int k  = item >> 5;
            int f4 = (item & 31) * 4;
            *(float4*)&Bs[k][f4] = *(const float4*)&W12[(size_t)(kt * 32 + k) * 128 + f4];
        }
        __syncthreads();

#pragma unroll 4
        for (int k = 0; k < 32; k++) {
            float4 a0 = *(const float4*)&As[k][ty * 8];
            float4 a1 = *(const float4*)&As[k][ty * 8 + 4];
            ulonglong2 b0 = *(const ulonglong2*)&Bs[k][tx * 8];
            ulonglong2 b1 = *(const ulonglong2*)&Bs[k][tx * 8 + 4];
            float av[8] = {a0.x, a0.y, a0.z, a0.w, a1.x, a1.y, a1.z, a1.w};
#pragma unroll
            for (int i = 0; i < 8; i++) {
                ull ap = pack2(av[i], av[i]);
                fma2(acc[i][0], ap, b0.x);
                fma2(acc[i][1], ap, b0.y);
                fma2(acc[i][2], ap, b1.x);
                fma2(acc[i][3], ap, b1.y);
            }
        }
        __syncthreads();
    }

    // ---- epilogue: embsum @ K1 (smem reuse) ----
    float* Es = &As[0][0];                     // Es[row*33 + i], 64*33 = 2112 <= 2176
    for (int s = tid; s < 64 * 32; s += 128) {
        int r = s >> 5, i2 = s & 31;
        Es[r * 33 + i2] = g_embsum[(size_t)(rowBase + r) * 32 + i2];
    }
    for (int s = tid; s < 32 * 128; s += 128) {
        int k = s >> 7, f = s & 127;
        Bs[k][f] = K1[s];
    }
    __syncthreads();

#pragma unroll 8
    for (int t = 0; t < 32; t++) {
        ulonglong2 b0 = *(const ulonglong2*)&Bs[t][tx * 8];
        ulonglong2 b1 = *(const ulonglong2*)&Bs[t][tx * 8 + 4];
#pragma unroll
        for (int i = 0; i < 8; i++) {
            float e = Es[(ty * 8 + i) * 33 + t];
            ull ap = pack2(e, e);
            fma2(acc[i][0], ap, b0.x);
            fma2(acc[i][1], ap, b0.y);
            fma2(acc[i][2], ap, b1.x);
            fma2(acc[i][3], ap, b1.y);
        }
    }

    float bv[8];
#pragma unroll
    for (int j = 0; j < 8; j++) bv[j] = bias[tx * 8 + j];

#pragma unroll
    for (int i = 0; i < 8; i++) {
        size_t ro = (size_t)(rowBase + ty * 8 + i) * 128 + tx * 8;
        float2 f0 = unpack2(acc[i][0]);
        float2 f1 = unpack2(acc[i][1]);
        float2 f2 = unpack2(acc[i][2]);
        float2 f3 = unpack2(acc[i][3]);
        float4 o0 = make_float4(f0.x + bv[0], f0.y + bv[1], f1.x + bv[2], f1.y + bv[3]);
        float4 o1 = make_float4(f2.x + bv[4], f2.y + bv[5], f3.x + bv[6], f3.y + bv[7]);
        *(float4*)&out[ro]     = o0;
        *(float4*)&out[ro + 4] = o1;
    }
}

// ============================================================================
extern "C" void kernel_launch(void* const* d_in, const int* in_sizes, int n_in,
                              void* d_out, int out_size)
{
    const float* attr  = (const float*)d_in[0];
    const float* frame = (const float*)d_in[1];
    const int*   aidx  = (const int*)  d_in[2];
    // d_in[3] = labels (unused)
    const float* gkc   = (const float*)d_in[4];
    const float* gkp   = (const float*)d_in[5];
    const float* W12   = (const float*)d_in[6];
    const float* K1    = (const float*)d_in[7];
    const float* bias  = (const float*)d_in[8];
    float* out = (float*)d_out;

    pack_centers<<<64, 256>>>(frame);
    knn_kernel<<<2048, 256>>>();
    feat_kernel<<<NB * NL, 128>>>(attr, frame, aidx, gkc, gkp);
    gemm_kernel<<<256, 128>>>(W12, K1, bias, out);
}